// round 8
// baseline (speedup 1.0000x reference)
#include <cuda_runtime.h>
#include <cstddef>

// Ghost-cell padding with affine boundary conditions.
// arr: (4, 4096, 4096) f32 -> out: (4, 4098, 4098) f32
//
// Round-8 change vs round-6 (single variable): persistent CTAs.
// Grid = 592 (148 SMs x 4 CTAs); each CTA grid-strides over the 8196
// (field, row-pair) work items, preserving the round-6 winning burst
// structure per iteration: 32 KB read burst -> barrier -> 32 KB write
// burst. Eliminates ~13 wave transitions (~2360 cyc each) and the
// partial-wave tail; two cheap barriers per iteration protect smem reuse.

static constexpr int F  = 4;
static constexpr int NX = 4096;
static constexpr int NY = 4096;
static constexpr int PX = NX + 2;   // 4098
static constexpr int PY = NY + 2;   // 4098

static constexpr int THREADS = 512;
static constexpr int RPB     = 2;              // rows per iteration (4098 = 2*2049)
static constexpr int PAIRS_PER_F = PX / RPB;   // 2049
static constexpr int WORK  = F * PAIRS_PER_F;  // 8196 work items
static constexpr int CTAS  = 148 * 4;          // persistent grid

__global__ void __launch_bounds__(THREADS)
ghost_pad_kernel(const float* __restrict__ arr,
                 const float* __restrict__ bc,   // bc_const  flat [axis*2+side]
                 const float* __restrict__ bf,   // bc_factor flat [axis*2+side]
                 float* __restrict__ out)
{
    __shared__ float s[RPB][NY];    // staged input rows (32 KB)

    const int t = threadIdx.x;

    for (int w = blockIdx.x; w < WORK; w += CTAS) {
        const int f    = w / PAIRS_PER_F;
        const int row0 = (w - f * PAIRS_PER_F) * RPB;

        // Phase 1: stage RPB source rows into smem (aligned 16B loads).
        #pragma unroll
        for (int rr = 0; rr < RPB; rr++) {
            const int row = row0 + rr;
            const int src = (row == 0) ? 0
                          : ((row == PX - 1) ? (NX - 1) : (row - 1));
            const float* __restrict__ a = arr + ((size_t)f * NX + src) * NY;
            #pragma unroll
            for (int i = 0; i < 2; i++) {
                const int k = 4 * (t + i * THREADS);      // 0..4092, mult of 4
                *reinterpret_cast<float4*>(&s[rr][k]) =
                    __ldcs(reinterpret_cast<const float4*>(a + k));
            }
        }
        __syncthreads();

        // Phase 2: shifted smem reads + coalesced 8B streaming stores.
        #pragma unroll
        for (int rr = 0; rr < RPB; rr++) {
            const int row = row0 + rr;

            float fac, c, edgeL, edgeR;
            if (row == 0) {
                c = bc[0]; fac = bf[0];                   // top ghost row
                edgeL = 0.0f; edgeR = 0.0f;
            } else if (row == PX - 1) {
                c = bc[1]; fac = bf[1];                   // bottom ghost row
                edgeL = 0.0f; edgeR = 0.0f;
            } else {
                c = 0.0f; fac = 1.0f;                     // fma(1,x,0) == x
                edgeL = fmaf(bf[2], s[rr][0],      bc[2]);
                edgeR = fmaf(bf[3], s[rr][NY - 1], bc[3]);
            }

            // Row base offset = (f*PX + row) * 4098 -> always even,
            // so float2 stores at even j are 8B-aligned.
            float* __restrict__ orow = out + ((size_t)f * PX + row) * PY;

            #pragma unroll
            for (int i = 0; i < 4; i++) {
                const int j = 2 * (t + i * THREADS);      // 0..4094, even
                const float l0 = s[rr][(j == 0) ? 0 : (j - 1)];
                const float l1 = s[rr][j];
                float v0 = fmaf(fac, l0, c);
                if (j == 0) v0 = edgeL;                   // single thread
                const float v1 = fmaf(fac, l1, c);
                __stcs(reinterpret_cast<float2*>(orow + j), make_float2(v0, v1));
            }

            // Tail pair: positions 4096 (from a[4095]) and 4097 (right edge).
            if (t == 0) {
                __stcs(reinterpret_cast<float2*>(orow + (PY - 2)),
                       make_float2(fmaf(fac, s[rr][NY - 1], c), edgeR));
            }
        }
        __syncthreads();            // smem reuse guard for next iteration
    }
}

extern "C" void kernel_launch(void* const* d_in, const int* in_sizes, int n_in,
                              void* d_out, int out_size)
{
    const float* arr       = (const float*)d_in[0];
    const float* bc_const  = (const float*)d_in[1];
    const float* bc_factor = (const float*)d_in[2];
    float* out             = (float*)d_out;

    ghost_pad_kernel<<<CTAS, THREADS>>>(arr, bc_const, bc_factor, out);
}

// round 9
// speedup vs baseline: 1.1277x; 1.1277x over previous
#include <cuda_runtime.h>
#include <cstddef>

// Ghost-cell padding with affine boundary conditions.
// arr: (4, 4096, 4096) f32 -> out: (4, 4098, 4098) f32
//
// Round-9 change vs round-6: keep the winning 2-rows-per-CTA burst structure
// (32 KB reads then 32 KB writes per CTA) but stage in REGISTERS instead of
// shared memory: 1024 threads/CTA, 8 staged floats per thread (2 rows x 2
// float2 pairs). All loads front-batch, stores drain off the scoreboard —
// no __syncthreads (R8 showed barriers hurt), no smem round trip. Scalar
// 8B-stride loads were shown equivalent to vectorized ones in R2 vs R4.

static constexpr int F  = 4;
static constexpr int NX = 4096;
static constexpr int NY = 4096;
static constexpr int PX = NX + 2;   // 4098
static constexpr int PY = NY + 2;   // 4098

static constexpr int THREADS = 1024;
static constexpr int RPB     = 2;   // padded rows per block; 4098 = 2 * 2049

__global__ void __launch_bounds__(THREADS)
ghost_pad_kernel(const float* __restrict__ arr,
                 const float* __restrict__ bc,   // bc_const  flat [axis*2+side]
                 const float* __restrict__ bf,   // bc_factor flat [axis*2+side]
                 float* __restrict__ out)
{
    const int row0 = blockIdx.x * RPB;   // first padded row of this block
    const int f    = blockIdx.y;         // field
    const int t    = threadIdx.x;

    // Per-row source pointers and affine coefficients.
    const float* a[RPB];
    float fac[RPB], c[RPB];
    bool ghostrow[RPB];
    #pragma unroll
    for (int rr = 0; rr < RPB; rr++) {
        const int row = row0 + rr;
        const int src = (row == 0) ? 0 : ((row == PX - 1) ? (NX - 1) : (row - 1));
        a[rr] = arr + ((size_t)f * NX + src) * NY;
        if (row == 0)            { c[rr] = bc[0]; fac[rr] = bf[0]; ghostrow[rr] = true; }
        else if (row == PX - 1)  { c[rr] = bc[1]; fac[rr] = bf[1]; ghostrow[rr] = true; }
        else                     { c[rr] = 0.0f;  fac[rr] = 1.0f;  ghostrow[rr] = false; }
    }

    // Phase 1: front-batched register staging.
    // Pairs (j, j+1), j = 2*(t + i*1024), covers output positions 0..4095.
    float l0[RPB][2], l1[RPB][2];
    #pragma unroll
    for (int rr = 0; rr < RPB; rr++) {
        #pragma unroll
        for (int i = 0; i < 2; i++) {
            const int j = 2 * (t + i * THREADS);          // even, 0..4094
            l0[rr][i] = __ldcs(a[rr] + ((j == 0) ? 0 : (j - 1)));
            l1[rr][i] = __ldcs(a[rr] + j);
        }
    }

    // Phase 2: coalesced 8B streaming stores (row base offsets always even).
    #pragma unroll
    for (int rr = 0; rr < RPB; rr++) {
        const int row = row0 + rr;
        float* __restrict__ orow = out + ((size_t)f * PX + row) * PY;

        #pragma unroll
        for (int i = 0; i < 2; i++) {
            const int j = 2 * (t + i * THREADS);
            float v0 = fmaf(fac[rr], l0[rr][i], c[rr]);
            const float v1 = fmaf(fac[rr], l1[rr][i], c[rr]);
            if (j == 0) {
                // Left edge: zero corner for ghost rows, axis-1 ghost otherwise.
                v0 = ghostrow[rr] ? 0.0f
                                  : fmaf(bf[2], l1[rr][0], bc[2]);  // l1[rr][0] = a[0]
            }
            __stcs(reinterpret_cast<float2*>(orow + j), make_float2(v0, v1));
        }

        // Tail pair: positions 4096 (affine of a[4095]) and 4097 (right edge).
        if (t == 0) {
            const float alast = __ldcs(a[rr] + (NY - 1));
            const float v0 = fmaf(fac[rr], alast, c[rr]);
            const float edgeR = ghostrow[rr] ? 0.0f
                                             : fmaf(bf[3], alast, bc[3]);
            __stcs(reinterpret_cast<float2*>(orow + (PY - 2)),
                   make_float2(v0, edgeR));
        }
    }
}

extern "C" void kernel_launch(void* const* d_in, const int* in_sizes, int n_in,
                              void* d_out, int out_size)
{
    const float* arr       = (const float*)d_in[0];
    const float* bc_const  = (const float*)d_in[1];
    const float* bc_factor = (const float*)d_in[2];
    float* out             = (float*)d_out;

    dim3 grid(PX / RPB, F);         // 2049 x 4
    ghost_pad_kernel<<<grid, THREADS>>>(arr, bc_const, bc_factor, out);
}